// round 4
// baseline (speedup 1.0000x reference)
#include <cuda_runtime.h>
#include <math.h>

// Problem constants (shapes fixed by dataset)
#define BQ   2048
#define NQ   64
#define ZD   64
#define RD   128
#define HQ   128

// r[b][j] produced by encoder, consumed by main loop
__device__ float g_r[BQ * RD];

__device__ __forceinline__ float sigm(float x) {
    return __fdividef(1.0f, 1.0f + __expf(-x));
}
__device__ __forceinline__ float silu_f(float x) {
    return x * sigm(x);
}

// ===================== Encoder kernel =====================
// 4 batch elements per block, 512 threads (4 groups x 128).
// Thread j of group g owns hidden unit j; 8 context points register-blocked.
struct EncSmem {
    float We1[3 * 128];
    float We2[128 * 128];
    float We3[128 * 128];
    float h1s[4][128 * 8];
    float h2s[4][128 * 8];
    float xs[4][64 * 2];
    float ys[4][64];
    float ms[4][64];
};

__global__ void __launch_bounds__(512, 1)
enc_kernel(const float* __restrict__ xg, const float* __restrict__ yg,
           const float* __restrict__ mg,
           const float* __restrict__ We1g, const float* __restrict__ be1g,
           const float* __restrict__ We2g, const float* __restrict__ be2g,
           const float* __restrict__ We3g, const float* __restrict__ be3g)
{
    extern __shared__ char smem_raw[];
    EncSmem& S = *reinterpret_cast<EncSmem*>(smem_raw);
    const int tid = threadIdx.x;
    const int g = tid >> 7, j = tid & 127;
    const int b = blockIdx.x * 4 + g;

    for (int idx = tid; idx < 3 * 128; idx += 512) S.We1[idx] = We1g[idx];
    for (int idx = tid; idx < 128 * 128; idx += 512) S.We2[idx] = We2g[idx];
    for (int idx = tid; idx < 128 * 128; idx += 512) S.We3[idx] = We3g[idx];
    for (int idx = j; idx < 64; idx += 128) {
        S.xs[g][idx * 2]     = xg[(b * 64 + idx) * 2];
        S.xs[g][idx * 2 + 1] = xg[(b * 64 + idx) * 2 + 1];
        S.ys[g][idx] = yg[b * 64 + idx];
        S.ms[g][idx] = mg[b * 64 + idx];
    }
    const float be1j = be1g[j], be2j = be2g[j], be3j = be3g[j];
    const float w0j = We1g[j], w1j = We1g[128 + j], w2j = We1g[256 + j];
    __syncthreads();

    float racc = 0.f;
    for (int c = 0; c < 8; c++) {
        const int n0 = c * 8;
        float hv[8];
        #pragma unroll
        for (int nk = 0; nk < 8; nk++) {
            int n = n0 + nk;
            float x0 = S.xs[g][n * 2], x1 = S.xs[g][n * 2 + 1], y = S.ys[g][n];
            float pre = x0 * w0j + x1 * w1j + y * w2j + be1j;
            hv[nk] = silu_f(pre);
        }
        *(float4*)&S.h1s[g][j * 8]     = make_float4(hv[0], hv[1], hv[2], hv[3]);
        *(float4*)&S.h1s[g][j * 8 + 4] = make_float4(hv[4], hv[5], hv[6], hv[7]);
        __syncthreads();

        float acc[8];
        #pragma unroll
        for (int nk = 0; nk < 8; nk++) acc[nk] = be2j;
        #pragma unroll 8
        for (int i = 0; i < 128; i++) {
            float w = S.We2[i * 128 + j];
            float4 a = *(const float4*)&S.h1s[g][i * 8];
            float4 bb = *(const float4*)&S.h1s[g][i * 8 + 4];
            acc[0] += w * a.x;  acc[1] += w * a.y;  acc[2] += w * a.z;  acc[3] += w * a.w;
            acc[4] += w * bb.x; acc[5] += w * bb.y; acc[6] += w * bb.z; acc[7] += w * bb.w;
        }
        #pragma unroll
        for (int nk = 0; nk < 8; nk++) hv[nk] = silu_f(acc[nk]);
        *(float4*)&S.h2s[g][j * 8]     = make_float4(hv[0], hv[1], hv[2], hv[3]);
        *(float4*)&S.h2s[g][j * 8 + 4] = make_float4(hv[4], hv[5], hv[6], hv[7]);
        __syncthreads();

        float acc3[8];
        #pragma unroll
        for (int nk = 0; nk < 8; nk++) acc3[nk] = be3j;
        #pragma unroll 8
        for (int i = 0; i < 128; i++) {
            float w = S.We3[i * 128 + j];
            float4 a = *(const float4*)&S.h2s[g][i * 8];
            float4 bb = *(const float4*)&S.h2s[g][i * 8 + 4];
            acc3[0] += w * a.x;  acc3[1] += w * a.y;  acc3[2] += w * a.z;  acc3[3] += w * a.w;
            acc3[4] += w * bb.x; acc3[5] += w * bb.y; acc3[6] += w * bb.z; acc3[7] += w * bb.w;
        }
        #pragma unroll
        for (int nk = 0; nk < 8; nk++) racc += acc3[nk] * S.ms[g][n0 + nk];
        // no trailing sync needed: next write to h1s is guarded by the sync after it
    }
    float msum = 0.f;
    #pragma unroll 8
    for (int n = 0; n < 64; n++) msum += S.ms[g][n];
    g_r[b * 128 + j] = racc / fmaxf(msum, 1e-6f);
}

// ===================== Main sampler kernel =====================
// 4 batch elements per block, 512 threads. 20 Langevin steps fully in-block.
struct MainSmem {
    float Wd1[66 * 128];     // forward layout [i][j]
    float Wd2[128 * 128];    // forward layout [i][j]
    float Wd2T[128 * 129];   // transposed (padded): Wd2T[m*129+j] = Wd2[j][m]
    float h1s[4][128 * 8];
    float g2s[4][128 * 8];
    float xs[4][64 * 2];
    float ys[4][64];
    float ms[4][64];
    float zs[64 * 4];        // z interleaved by group: zs[k*4+g]
    float es[4][8];
    float partials[4][32];
    float g1sums[4][128];
    float gzs[64 * 4];       // interleaved by group
    float c1s[128 * 4];      // drift layer-1 precomputed (r-part + bias), float4 per j
    float f1s[128 * 4];
    float f2s[128 * 4];
    float rtmp[128 * 4];
};

__global__ void __launch_bounds__(512, 1)
main_kernel(const float* __restrict__ xg, const float* __restrict__ yg,
            const float* __restrict__ mg, const float* __restrict__ z0g,
            const float* __restrict__ noiseg,
            const float* __restrict__ Wd1g, const float* __restrict__ bd1g,
            const float* __restrict__ Wd2g, const float* __restrict__ bd2g,
            const float* __restrict__ Wd3g, const float* __restrict__ bd3g,
            const float* __restrict__ Wf1g, const float* __restrict__ bf1g,
            const float* __restrict__ Wf2g, const float* __restrict__ bf2g,
            const float* __restrict__ Wf3g, const float* __restrict__ bf3g,
            float* __restrict__ outg, int steps, float dtf, float dcf)
{
    extern __shared__ char smem_raw[];
    MainSmem& S = *reinterpret_cast<MainSmem*>(smem_raw);
    const int tid = threadIdx.x;
    const int g = tid >> 7, j = tid & 127;
    const int b0 = blockIdx.x * 4;
    const int b = b0 + g;

    // -------- weight staging --------
    for (int idx = tid; idx < 66 * 128; idx += 512) S.Wd1[idx] = Wd1g[idx];
    for (int idx = tid; idx < 128 * 128; idx += 512) S.Wd2[idx] = Wd2g[idx];
    for (int idx = tid; idx < 128 * 128; idx += 512) {
        int r = idx >> 7, m = idx & 127;              // Wd2g[r][m]
        S.Wd2T[m * 129 + r] = Wd2g[idx];              // conflict-free (129 stride)
    }
    // -------- per-batch-element data --------
    for (int idx = j; idx < 64; idx += 128) {
        S.xs[g][idx * 2]     = xg[(b * 64 + idx) * 2];
        S.xs[g][idx * 2 + 1] = xg[(b * 64 + idx) * 2 + 1];
        S.ys[g][idx] = yg[b * 64 + idx];
        S.ms[g][idx] = mg[b * 64 + idx];
        S.zs[idx * 4 + g] = z0g[b * 64 + idx];
    }
    for (int idx = j; idx < 128; idx += 128) S.rtmp[idx * 4 + g] = g_r[b * 128 + idx];

    const float w64j = Wd1g[64 * 128 + j];
    const float w65j = Wd1g[65 * 128 + j];
    const float bd1j = bd1g[j], bd2j = bd2g[j];
    const float wd3j = Wd3g[j];
    const float bd3v = bd3g[0];
    const float bf2j = bf2g[j];
    const float wtj  = Wf1g[192 * 128 + j];   // t-row of Wf1
    __syncthreads();

    // -------- drift layer-1 r-part precompute: c1[g][j] = r[g]@Wf1r + bf1[j] --------
    if (tid < 128) {
        float bf1j = bf1g[j];
        float4 acc = make_float4(bf1j, bf1j, bf1j, bf1j);
        #pragma unroll 4
        for (int i = 0; i < 128; i++) {
            float w = Wf1g[(64 + i) * 128 + j];
            float4 rv = *(const float4*)&S.rtmp[i * 4];
            acc.x += w * rv.x; acc.y += w * rv.y; acc.z += w * rv.z; acc.w += w * rv.w;
        }
        *(float4*)&S.c1s[j * 4] = acc;
    }
    __syncthreads();

    // ======================= step loop =======================
    for (int s = 0; s < steps; s++) {
        const float t = (float)s * dtf;

        // z-part of decoder layer 1 (shared over all n)
        float zWj = 0.f;
        #pragma unroll 8
        for (int k = 0; k < 64; k++) zWj += S.zs[k * 4 + g] * S.Wd1[k * 128 + j];

        float G1sumj = 0.f;

        for (int c = 0; c < 8; c++) {
            const int n0 = c * 8;
            // ---- A: h1 = silu(zW + x-part + b) ----
            float d1r[8], hv[8];
            #pragma unroll
            for (int nk = 0; nk < 8; nk++) {
                int n = n0 + nk;
                float x0 = S.xs[g][n * 2], x1 = S.xs[g][n * 2 + 1];
                float pre = zWj + x0 * w64j + x1 * w65j + bd1j;
                float sg = sigm(pre);
                float h = pre * sg;
                d1r[nk] = sg + h * (1.f - sg);   // silu'(pre1)
                hv[nk] = h;
            }
            *(float4*)&S.h1s[g][j * 8]     = make_float4(hv[0], hv[1], hv[2], hv[3]);
            *(float4*)&S.h1s[g][j * 8 + 4] = make_float4(hv[4], hv[5], hv[6], hv[7]);
            __syncthreads();

            // ---- B: pre2 = h1 @ Wd2 + b2 ; h2 = silu ; yhat partial reduce ----
            float acc[8];
            #pragma unroll
            for (int nk = 0; nk < 8; nk++) acc[nk] = bd2j;
            #pragma unroll 8
            for (int i = 0; i < 128; i++) {
                float w = S.Wd2[i * 128 + j];
                float4 a = *(const float4*)&S.h1s[g][i * 8];
                float4 bb = *(const float4*)&S.h1s[g][i * 8 + 4];
                acc[0] += w * a.x;  acc[1] += w * a.y;  acc[2] += w * a.z;  acc[3] += w * a.w;
                acc[4] += w * bb.x; acc[5] += w * bb.y; acc[6] += w * bb.z; acc[7] += w * bb.w;
            }
            float d2f[8], yv[8];
            #pragma unroll
            for (int nk = 0; nk < 8; nk++) {
                float sg = sigm(acc[nk]);
                float h2 = acc[nk] * sg;
                d2f[nk] = wd3j * (sg + h2 * (1.f - sg));  // Wd3[j]*silu'(pre2)
                yv[nk] = h2 * wd3j;
            }
            #pragma unroll
            for (int off = 16; off > 0; off >>= 1) {
                #pragma unroll
                for (int nk = 0; nk < 8; nk++)
                    yv[nk] += __shfl_xor_sync(0xffffffffu, yv[nk], off);
            }
            if ((j & 31) == 0) {
                int w = j >> 5;
                #pragma unroll
                for (int nk = 0; nk < 8; nk++) S.partials[g][w * 8 + nk] = yv[nk];
            }
            __syncthreads();

            // ---- C: residual e = (yhat - y)*mask ----
            if (j < 8) {
                int nk = j;
                float yh = S.partials[g][nk] + S.partials[g][8 + nk]
                         + S.partials[g][16 + nk] + S.partials[g][24 + nk] + bd3v;
                float e = (yh - S.ys[g][n0 + nk]) * S.ms[g][n0 + nk];
                S.es[g][nk] = e;
            }
            __syncthreads();

            // ---- D: g2 = e * Wd3 * silu'(pre2) ----
            float g2v[8];
            #pragma unroll
            for (int nk = 0; nk < 8; nk++) g2v[nk] = S.es[g][nk] * d2f[nk];
            *(float4*)&S.g2s[g][j * 8]     = make_float4(g2v[0], g2v[1], g2v[2], g2v[3]);
            *(float4*)&S.g2s[g][j * 8 + 4] = make_float4(g2v[4], g2v[5], g2v[6], g2v[7]);
            __syncthreads();

            // ---- E: g1 = (g2 @ Wd2^T) * silu'(pre1), accumulate over n ----
            float acc2[8];
            #pragma unroll
            for (int nk = 0; nk < 8; nk++) acc2[nk] = 0.f;
            #pragma unroll 8
            for (int m = 0; m < 128; m++) {
                float w = S.Wd2T[m * 129 + j];
                float4 a = *(const float4*)&S.g2s[g][m * 8];
                float4 bb = *(const float4*)&S.g2s[g][m * 8 + 4];
                acc2[0] += w * a.x;  acc2[1] += w * a.y;  acc2[2] += w * a.z;  acc2[3] += w * a.w;
                acc2[4] += w * bb.x; acc2[5] += w * bb.y; acc2[6] += w * bb.z; acc2[7] += w * bb.w;
            }
            #pragma unroll
            for (int nk = 0; nk < 8; nk++) G1sumj += acc2[nk] * d1r[nk];
            // no trailing sync needed (next conflicting write is 3 barriers away)
        }

        // ---- gz[k] = sum_j G1sum[j] * Wd1[k][j]  (warp-cooperative) ----
        S.g1sums[g][j] = G1sumj;
        __syncthreads();
        {
            int warpg = j >> 5, lane = j & 31;
            for (int kk = 0; kk < 16; kk++) {
                int k = warpg * 16 + kk;
                float a = 0.f;
                #pragma unroll
                for (int q = 0; q < 4; q++) {
                    int jj = q * 32 + lane;
                    a += S.g1sums[g][jj] * S.Wd1[k * 128 + jj];
                }
                #pragma unroll
                for (int off = 16; off > 0; off >>= 1)
                    a += __shfl_xor_sync(0xffffffffu, a, off);
                if (lane == 0) S.gzs[k * 4 + g] = a;
            }
        }
        __syncthreads();

        // ---- drift (block-cooperative, 4 batch elements via float4) ----
        if (tid < 128) {
            float4 acc = *(const float4*)&S.c1s[j * 4];
            #pragma unroll 4
            for (int k = 0; k < 64; k++) {
                float w = Wf1g[k * 128 + j];
                float4 zv = *(const float4*)&S.zs[k * 4];
                acc.x += w * zv.x; acc.y += w * zv.y; acc.z += w * zv.z; acc.w += w * zv.w;
            }
            float tw = t * wtj;
            acc.x = silu_f(acc.x + tw); acc.y = silu_f(acc.y + tw);
            acc.z = silu_f(acc.z + tw); acc.w = silu_f(acc.w + tw);
            *(float4*)&S.f1s[j * 4] = acc;
        }
        __syncthreads();
        if (tid < 128) {
            float4 acc = make_float4(bf2j, bf2j, bf2j, bf2j);
            #pragma unroll 4
            for (int i = 0; i < 128; i++) {
                float w = Wf2g[i * 128 + j];
                float4 v = *(const float4*)&S.f1s[i * 4];
                acc.x += w * v.x; acc.y += w * v.y; acc.z += w * v.z; acc.w += w * v.w;
            }
            acc.x = silu_f(acc.x); acc.y = silu_f(acc.y);
            acc.z = silu_f(acc.z); acc.w = silu_f(acc.w);
            *(float4*)&S.f2s[j * 4] = acc;
        }
        __syncthreads();
        if (tid < 64) {
            int k = tid;
            float bf3k = bf3g[k];
            float4 acc = make_float4(bf3k, bf3k, bf3k, bf3k);
            #pragma unroll 4
            for (int jj = 0; jj < 128; jj++) {
                float w = Wf3g[jj * 64 + k];
                float4 v = *(const float4*)&S.f2s[jj * 4];
                acc.x += w * v.x; acc.y += w * v.y; acc.z += w * v.z; acc.w += w * v.w;
            }
            float bvals[4] = {acc.x, acc.y, acc.z, acc.w};
            #pragma unroll
            for (int gg = 0; gg < 4; gg++) {
                float zold = S.zs[k * 4 + gg];
                float gv = zold + t * S.gzs[k * 4 + gg];
                gv = fminf(fmaxf(gv, -100.f), 100.f);
                float nz = noiseg[((size_t)s * BQ + (b0 + gg)) * 64 + k];
                S.zs[k * 4 + gg] = zold + (bvals[gg] - gv) * dtf + dcf * nz;
            }
        }
        __syncthreads();
    }

    // ---- write z_final ----
    for (int idx = j; idx < 64; idx += 128)
        outg[(size_t)b * 64 + idx] = S.zs[idx * 4 + g];
}

// ===================== launcher =====================
extern "C" void kernel_launch(void* const* d_in, const int* in_sizes, int n_in,
                              void* d_out, int out_size)
{
    const float* x_ctx  = (const float*)d_in[0];
    const float* y_ctx  = (const float*)d_in[1];
    const float* mask   = (const float*)d_in[2];
    const float* z0     = (const float*)d_in[3];
    const float* noises = (const float*)d_in[4];
    const float* We1 = (const float*)d_in[5];  const float* be1 = (const float*)d_in[6];
    const float* We2 = (const float*)d_in[7];  const float* be2 = (const float*)d_in[8];
    const float* We3 = (const float*)d_in[9];  const float* be3 = (const float*)d_in[10];
    const float* Wd1 = (const float*)d_in[11]; const float* bd1 = (const float*)d_in[12];
    const float* Wd2 = (const float*)d_in[13]; const float* bd2 = (const float*)d_in[14];
    const float* Wd3 = (const float*)d_in[15]; const float* bd3 = (const float*)d_in[16];
    const float* Wf1 = (const float*)d_in[17]; const float* bf1 = (const float*)d_in[18];
    const float* Wf2 = (const float*)d_in[19]; const float* bf2 = (const float*)d_in[20];
    const float* Wf3 = (const float*)d_in[21]; const float* bf3 = (const float*)d_in[22];
    float* out = (float*)d_out;

    int steps = in_sizes[4] / (BQ * ZD);
    if (steps <= 0) steps = 20;
    float dtf = (float)(1.0 / (double)steps);
    float dcf = (float)sqrt(2.0 / (double)steps);

    cudaFuncSetAttribute(enc_kernel, cudaFuncAttributeMaxDynamicSharedMemorySize,
                         (int)sizeof(EncSmem));
    cudaFuncSetAttribute(main_kernel, cudaFuncAttributeMaxDynamicSharedMemorySize,
                         (int)sizeof(MainSmem));

    enc_kernel<<<BQ / 4, 512, sizeof(EncSmem)>>>(
        x_ctx, y_ctx, mask, We1, be1, We2, be2, We3, be3);

    main_kernel<<<BQ / 4, 512, sizeof(MainSmem)>>>(
        x_ctx, y_ctx, mask, z0, noises,
        Wd1, bd1, Wd2, bd2, Wd3, bd3,
        Wf1, bf1, Wf2, bf2, Wf3, bf3,
        out, steps, dtf, dcf);
}

// round 8
// speedup vs baseline: 1.5365x; 1.5365x over previous
#include <cuda_runtime.h>
#include <math.h>

#define BQ   2048
#define NQ   64
#define ZD   64
#define RD   128
#define HQ   128

__device__ float g_r[BQ * RD];

__device__ __forceinline__ float sigm(float x) {
    return __fdividef(1.0f, 1.0f + __expf(-x));
}
__device__ __forceinline__ float silu_f(float x) {
    return x * sigm(x);
}

// ---- packed fp32x2 helpers (Blackwell FFMA2) ----
__device__ __forceinline__ unsigned long long pk2(float x) {
    unsigned long long r;
    asm("mov.b64 %0, {%1, %1};" : "=l"(r) : "f"(x));
    return r;
}
__device__ __forceinline__ unsigned long long fma2(unsigned long long a,
                                                   unsigned long long b,
                                                   unsigned long long c) {
    unsigned long long d;
    asm("fma.rn.f32x2 %0, %1, %2, %3;" : "=l"(d) : "l"(a), "l"(b), "l"(c));
    return d;
}
__device__ __forceinline__ void up2(unsigned long long v, float& lo, float& hi) {
    asm("mov.b64 {%0, %1}, %2;" : "=f"(lo), "=f"(hi) : "l"(v));
}

// ===================== Encoder kernel (unchanged, passed R4) =====================
struct EncSmem {
    float We1[3 * 128];
    float We2[128 * 128];
    float We3[128 * 128];
    float h1s[4][128 * 8];
    float h2s[4][128 * 8];
    float xs[4][64 * 2];
    float ys[4][64];
    float ms[4][64];
};

__global__ void __launch_bounds__(512, 1)
enc_kernel(const float* __restrict__ xg, const float* __restrict__ yg,
           const float* __restrict__ mg,
           const float* __restrict__ We1g, const float* __restrict__ be1g,
           const float* __restrict__ We2g, const float* __restrict__ be2g,
           const float* __restrict__ We3g, const float* __restrict__ be3g)
{
    extern __shared__ char smem_raw[];
    EncSmem& S = *reinterpret_cast<EncSmem*>(smem_raw);
    const int tid = threadIdx.x;
    const int g = tid >> 7, j = tid & 127;
    const int b = blockIdx.x * 4 + g;

    for (int idx = tid; idx < 3 * 128; idx += 512) S.We1[idx] = We1g[idx];
    for (int idx = tid; idx < 128 * 128; idx += 512) S.We2[idx] = We2g[idx];
    for (int idx = tid; idx < 128 * 128; idx += 512) S.We3[idx] = We3g[idx];
    for (int idx = j; idx < 64; idx += 128) {
        S.xs[g][idx * 2]     = xg[(b * 64 + idx) * 2];
        S.xs[g][idx * 2 + 1] = xg[(b * 64 + idx) * 2 + 1];
        S.ys[g][idx] = yg[b * 64 + idx];
        S.ms[g][idx] = mg[b * 64 + idx];
    }
    const float be1j = be1g[j], be2j = be2g[j], be3j = be3g[j];
    const float w0j = We1g[j], w1j = We1g[128 + j], w2j = We1g[256 + j];
    __syncthreads();

    float racc = 0.f;
    for (int c = 0; c < 8; c++) {
        const int n0 = c * 8;
        float hv[8];
        #pragma unroll
        for (int nk = 0; nk < 8; nk++) {
            int n = n0 + nk;
            float x0 = S.xs[g][n * 2], x1 = S.xs[g][n * 2 + 1], y = S.ys[g][n];
            float pre = x0 * w0j + x1 * w1j + y * w2j + be1j;
            hv[nk] = silu_f(pre);
        }
        *(float4*)&S.h1s[g][j * 8]     = make_float4(hv[0], hv[1], hv[2], hv[3]);
        *(float4*)&S.h1s[g][j * 8 + 4] = make_float4(hv[4], hv[5], hv[6], hv[7]);
        __syncthreads();

        float acc[8];
        #pragma unroll
        for (int nk = 0; nk < 8; nk++) acc[nk] = be2j;
        #pragma unroll 8
        for (int i = 0; i < 128; i++) {
            float w = S.We2[i * 128 + j];
            float4 a = *(const float4*)&S.h1s[g][i * 8];
            float4 bb = *(const float4*)&S.h1s[g][i * 8 + 4];
            acc[0] += w * a.x;  acc[1] += w * a.y;  acc[2] += w * a.z;  acc[3] += w * a.w;
            acc[4] += w * bb.x; acc[5] += w * bb.y; acc[6] += w * bb.z; acc[7] += w * bb.w;
        }
        #pragma unroll
        for (int nk = 0; nk < 8; nk++) hv[nk] = silu_f(acc[nk]);
        *(float4*)&S.h2s[g][j * 8]     = make_float4(hv[0], hv[1], hv[2], hv[3]);
        *(float4*)&S.h2s[g][j * 8 + 4] = make_float4(hv[4], hv[5], hv[6], hv[7]);
        __syncthreads();

        float acc3[8];
        #pragma unroll
        for (int nk = 0; nk < 8; nk++) acc3[nk] = be3j;
        #pragma unroll 8
        for (int i = 0; i < 128; i++) {
            float w = S.We3[i * 128 + j];
            float4 a = *(const float4*)&S.h2s[g][i * 8];
            float4 bb = *(const float4*)&S.h2s[g][i * 8 + 4];
            acc3[0] += w * a.x;  acc3[1] += w * a.y;  acc3[2] += w * a.z;  acc3[3] += w * a.w;
            acc3[4] += w * bb.x; acc3[5] += w * bb.y; acc3[6] += w * bb.z; acc3[7] += w * bb.w;
        }
        #pragma unroll
        for (int nk = 0; nk < 8; nk++) racc += acc3[nk] * S.ms[g][n0 + nk];
    }
    float msum = 0.f;
    #pragma unroll 8
    for (int n = 0; n < 64; n++) msum += S.ms[g][n];
    g_r[b * 128 + j] = racc / fmaxf(msum, 1e-6f);
}

// ===================== Main sampler kernel =====================
// 4 batch elements / block, 512 threads = 4 groups x (4 warps x 32 lanes).
// Tiled phases: warp = n-subtile (8 n), lane jg = j-subtile (4 j).
// Hot loops use packed fp32x2 FMA; activations are warp-broadcast LDS.
#define NPAD 36   // 32 data + 4 pad words per buf row (bank-spread, 16B aligned)

struct MainSmem {
    float Wd2[128 * 128];     // forward  [i][j]
    float Wd2T[128 * 128];    // backward [m][i] = Wd2[i][m]
    float buf[4][128 * NPAD]; // h1 (A->B) then g2 (D->E), [row][n], 32 n/chunk
    float zWs[4][128];        // zW+bd1 per j per step
    float x0s[4][64];
    float x1s[4][64];
    float ys[4][64];
    float ms[4][64];
    float zs[64 * 4];         // z interleaved by group
    float es[4][32];
    float g1parts[4][128][4]; // [g][i][warp]
    float g1sums[4][128];
    float gzs[64 * 4];
    float c1s[128 * 4];
    float f1s[128 * 4];       // also used as rtmp during init
    float f2s[128 * 4];
};

__global__ void __launch_bounds__(512, 1)
main_kernel(const float* __restrict__ xg, const float* __restrict__ yg,
            const float* __restrict__ mg, const float* __restrict__ z0g,
            const float* __restrict__ noiseg,
            const float* __restrict__ Wd1g, const float* __restrict__ bd1g,
            const float* __restrict__ Wd2g, const float* __restrict__ bd2g,
            const float* __restrict__ Wd3g, const float* __restrict__ bd3g,
            const float* __restrict__ Wf1g, const float* __restrict__ bf1g,
            const float* __restrict__ Wf2g, const float* __restrict__ bf2g,
            const float* __restrict__ Wf3g, const float* __restrict__ bf3g,
            float* __restrict__ outg, int steps, float dtf, float dcf)
{
    extern __shared__ char smem_raw[];
    MainSmem& S = *reinterpret_cast<MainSmem*>(smem_raw);
    const int tid = threadIdx.x;
    const int g   = tid >> 7;          // group (batch element within block)
    const int wg  = (tid >> 5) & 3;    // warp-in-group = n-subtile
    const int jg  = tid & 31;          // lane = j-subtile
    const int jg4 = jg * 4;
    const int jj  = tid & 127;         // scalar-phase j/i index
    const int b0 = blockIdx.x * 4;
    const int b = b0 + g;

    // -------- weight staging --------
    for (int idx = tid; idx < 128 * 128; idx += 512) S.Wd2[idx] = Wd2g[idx];
    for (int idx = tid; idx < 128 * 128; idx += 512) {
        int r = idx >> 7, m = idx & 127;         // Wd2g[r][m]
        S.Wd2T[m * 128 + r] = Wd2g[idx];         // one-time conflicted writes, OK
    }
    // -------- per-batch-element data --------
    for (int idx = jj; idx < 64; idx += 128) {
        S.x0s[g][idx] = xg[(b * 64 + idx) * 2];
        S.x1s[g][idx] = xg[(b * 64 + idx) * 2 + 1];
        S.ys[g][idx]  = yg[b * 64 + idx];
        S.ms[g][idx]  = mg[b * 64 + idx];
        S.zs[idx * 4 + g] = z0g[b * 64 + idx];
    }
    for (int idx = jj; idx < 128; idx += 128) S.f1s[idx * 4 + g] = g_r[b * 128 + idx];

    // per-lane constants for the thread's 4 j/i rows
    const float4 w64v = *(const float4*)&Wd1g[64 * 128 + jg4];
    const float4 w65v = *(const float4*)&Wd1g[65 * 128 + jg4];
    const float4 wd3v = *(const float4*)&Wd3g[jg4];
    const float4 bd2v = *(const float4*)&bd2g[jg4];
    const float bd3v = bd3g[0];
    const float bf2j = bf2g[jj];
    const float wtj  = Wf1g[192 * 128 + jj];
    __syncthreads();

    // drift layer-1 r-part precompute (f1s holds r during init)
    if (tid < 128) {
        float bf1j = bf1g[jj];
        float4 acc = make_float4(bf1j, bf1j, bf1j, bf1j);
        #pragma unroll 4
        for (int i = 0; i < 128; i++) {
            float w = Wf1g[(64 + i) * 128 + jj];
            float4 rv = *(const float4*)&S.f1s[i * 4];
            acc.x += w * rv.x; acc.y += w * rv.y; acc.z += w * rv.z; acc.w += w * rv.w;
        }
        *(float4*)&S.c1s[jj * 4] = acc;
    }
    __syncthreads();

    const float wd3a[4] = {wd3v.x, wd3v.y, wd3v.z, wd3v.w};
    const float w64a[4] = {w64v.x, w64v.y, w64v.z, w64v.w};
    const float w65a[4] = {w65v.x, w65v.y, w65v.z, w65v.w};
    const float bd2a[4] = {bd2v.x, bd2v.y, bd2v.z, bd2v.w};

    // ======================= step loop =======================
    for (int s = 0; s < steps; s++) {
        const float t = (float)s * dtf;

        // ---- zW[j] = bd1[j] + z @ Wd1z (global weights, L2-resident) ----
        {
            float zw = bd1g[jj];
            #pragma unroll 8
            for (int k = 0; k < 64; k++)
                zw += S.zs[k * 4 + g] * Wd1g[k * 128 + jj];
            S.zWs[g][jj] = zw;
        }
        __syncthreads();

        float G1p[4] = {0.f, 0.f, 0.f, 0.f};

        for (int c = 0; c < 2; c++) {
            const int nb = c * 32 + wg * 8;   // global n base for this thread's 8 n
            const int ab = wg * 8;            // act column base within chunk rows

            // ---- A: h1 = silu(zW + x-part), tile 4j x 8n ----
            {
                float4 zwv = *(const float4*)&S.zWs[g][jg4];
                const float zwa[4] = {zwv.x, zwv.y, zwv.z, zwv.w};
                float4 x0a = *(const float4*)&S.x0s[g][nb];
                float4 x0b = *(const float4*)&S.x0s[g][nb + 4];
                float4 x1a = *(const float4*)&S.x1s[g][nb];
                float4 x1b = *(const float4*)&S.x1s[g][nb + 4];
                float x0w[8] = {x0a.x, x0a.y, x0a.z, x0a.w, x0b.x, x0b.y, x0b.z, x0b.w};
                float x1w[8] = {x1a.x, x1a.y, x1a.z, x1a.w, x1b.x, x1b.y, x1b.z, x1b.w};
                #pragma unroll
                for (int q = 0; q < 4; q++) {
                    float hv[8];
                    #pragma unroll
                    for (int nq = 0; nq < 8; nq++) {
                        float pre = zwa[q] + x0w[nq] * w64a[q] + x1w[nq] * w65a[q];
                        hv[nq] = silu_f(pre);
                    }
                    float* row = &S.buf[g][(jg4 + q) * NPAD + ab];
                    *(float4*)row       = make_float4(hv[0], hv[1], hv[2], hv[3]);
                    *(float4*)(row + 4) = make_float4(hv[4], hv[5], hv[6], hv[7]);
                }
            }
            __syncthreads();

            // ---- B: pre2 = h1 @ Wd2 (+bd2); keep pre2 packed in acc ----
            unsigned long long acc[4][4];
            #pragma unroll
            for (int q = 0; q < 4; q++) {
                unsigned long long bq = pk2(bd2a[q]);
                acc[q][0] = bq; acc[q][1] = bq; acc[q][2] = bq; acc[q][3] = bq;
            }
            #pragma unroll 4
            for (int i = 0; i < 128; i++) {
                const ulonglong2* ap = (const ulonglong2*)&S.buf[g][i * NPAD + ab];
                ulonglong2 a0 = ap[0];
                ulonglong2 a1 = ap[1];
                float4 wv = *(const float4*)&S.Wd2[i * 128 + jg4];
                unsigned long long w;
                w = pk2(wv.x);
                acc[0][0] = fma2(w, a0.x, acc[0][0]); acc[0][1] = fma2(w, a0.y, acc[0][1]);
                acc[0][2] = fma2(w, a1.x, acc[0][2]); acc[0][3] = fma2(w, a1.y, acc[0][3]);
                w = pk2(wv.y);
                acc[1][0] = fma2(w, a0.x, acc[1][0]); acc[1][1] = fma2(w, a0.y, acc[1][1]);
                acc[1][2] = fma2(w, a1.x, acc[1][2]); acc[1][3] = fma2(w, a1.y, acc[1][3]);
                w = pk2(wv.z);
                acc[2][0] = fma2(w, a0.x, acc[2][0]); acc[2][1] = fma2(w, a0.y, acc[2][1]);
                acc[2][2] = fma2(w, a1.x, acc[2][2]); acc[2][3] = fma2(w, a1.y, acc[2][3]);
                w = pk2(wv.w);
                acc[3][0] = fma2(w, a0.x, acc[3][0]); acc[3][1] = fma2(w, a0.y, acc[3][1]);
                acc[3][2] = fma2(w, a1.x, acc[3][2]); acc[3][3] = fma2(w, a1.y, acc[3][3]);
            }
            // yhat partials: yv[nq] = sum over this lane's 4 j of h2*wd3
            {
                float yv[8] = {0.f,0.f,0.f,0.f,0.f,0.f,0.f,0.f};
                #pragma unroll
                for (int q = 0; q < 4; q++) {
                    #pragma unroll
                    for (int h = 0; h < 4; h++) {
                        float p0, p1;
                        up2(acc[q][h], p0, p1);
                        float s0 = sigm(p0), s1 = sigm(p1);
                        yv[2*h]     += p0 * s0 * wd3a[q];
                        yv[2*h + 1] += p1 * s1 * wd3a[q];
                    }
                }
                #pragma unroll
                for (int off = 16; off > 0; off >>= 1) {
                    #pragma unroll
                    for (int nq = 0; nq < 8; nq++)
                        yv[nq] += __shfl_xor_sync(0xffffffffu, yv[nq], off);
                }
                if (jg == 0) {
                    #pragma unroll
                    for (int nq = 0; nq < 8; nq++) {
                        int n = nb + nq;
                        float e = (yv[nq] + bd3v - S.ys[g][n]) * S.ms[g][n];
                        S.es[g][wg * 8 + nq] = e;
                    }
                }
            }
            __syncthreads();

            // ---- D: g2 = e * wd3 * silu'(pre2); write into buf (h1 dead) ----
            {
                float4 e0 = *(const float4*)&S.es[g][wg * 8];
                float4 e1 = *(const float4*)&S.es[g][wg * 8 + 4];
                float ew[8] = {e0.x, e0.y, e0.z, e0.w, e1.x, e1.y, e1.z, e1.w};
                #pragma unroll
                for (int q = 0; q < 4; q++) {
                    float gv[8];
                    #pragma unroll
                    for (int h = 0; h < 4; h++) {
                        float p0, p1;
                        up2(acc[q][h], p0, p1);
                        float s0 = sigm(p0), s1 = sigm(p1);
                        float h20 = p0 * s0, h21 = p1 * s1;
                        float d0 = wd3a[q] * (s0 + h20 * (1.f - s0));
                        float d1 = wd3a[q] * (s1 + h21 * (1.f - s1));
                        gv[2*h]     = ew[2*h]     * d0;
                        gv[2*h + 1] = ew[2*h + 1] * d1;
                    }
                    float* row = &S.buf[g][(jg4 + q) * NPAD + ab];
                    *(float4*)row       = make_float4(gv[0], gv[1], gv[2], gv[3]);
                    *(float4*)(row + 4) = make_float4(gv[4], gv[5], gv[6], gv[7]);
                }
            }
            __syncthreads();

            // ---- E: g1raw = g2 @ Wd2^T (rows i), fold silu'(pre1), accumulate ----
            {
                unsigned long long a2[4][4];
                #pragma unroll
                for (int q = 0; q < 4; q++)
                    a2[q][0] = a2[q][1] = a2[q][2] = a2[q][3] = 0ull;
                #pragma unroll 4
                for (int m = 0; m < 128; m++) {
                    const ulonglong2* ap = (const ulonglong2*)&S.buf[g][m * NPAD + ab];
                    ulonglong2 a0 = ap[0];
                    ulonglong2 a1 = ap[1];
                    float4 wv = *(const float4*)&S.Wd2T[m * 128 + jg4];
                    unsigned long long w;
                    w = pk2(wv.x);
                    a2[0][0] = fma2(w, a0.x, a2[0][0]); a2[0][1] = fma2(w, a0.y, a2[0][1]);
                    a2[0][2] = fma2(w, a1.x, a2[0][2]); a2[0][3] = fma2(w, a1.y, a2[0][3]);
                    w = pk2(wv.y);
                    a2[1][0] = fma2(w, a0.x, a2[1][0]); a2[1][1] = fma2(w, a0.y, a2[1][1]);
                    a2[1][2] = fma2(w, a1.x, a2[1][2]); a2[1][3] = fma2(w, a1.y, a2[1][3]);
                    w = pk2(wv.z);
                    a2[2][0] = fma2(w, a0.x, a2[2][0]); a2[2][1] = fma2(w, a0.y, a2[2][1]);
                    a2[2][2] = fma2(w, a1.x, a2[2][2]); a2[2][3] = fma2(w, a1.y, a2[2][3]);
                    w = pk2(wv.w);
                    a2[3][0] = fma2(w, a0.x, a2[3][0]); a2[3][1] = fma2(w, a0.y, a2[3][1]);
                    a2[3][2] = fma2(w, a1.x, a2[3][2]); a2[3][3] = fma2(w, a1.y, a2[3][3]);
                }
                // recompute pre1 (cheap) and fold silu'
                float4 zwv = *(const float4*)&S.zWs[g][jg4];
                const float zwa[4] = {zwv.x, zwv.y, zwv.z, zwv.w};
                float4 x0a = *(const float4*)&S.x0s[g][nb];
                float4 x0b = *(const float4*)&S.x0s[g][nb + 4];
                float4 x1a = *(const float4*)&S.x1s[g][nb];
                float4 x1b = *(const float4*)&S.x1s[g][nb + 4];
                float x0w[8] = {x0a.x, x0a.y, x0a.z, x0a.w, x0b.x, x0b.y, x0b.z, x0b.w};
                float x1w[8] = {x1a.x, x1a.y, x1a.z, x1a.w, x1b.x, x1b.y, x1b.z, x1b.w};
                #pragma unroll
                for (int q = 0; q < 4; q++) {
                    #pragma unroll
                    for (int h = 0; h < 4; h++) {
                        float r0, r1;
                        up2(a2[q][h], r0, r1);
                        int n0i = 2 * h, n1i = 2 * h + 1;
                        float pA = zwa[q] + x0w[n0i] * w64a[q] + x1w[n0i] * w65a[q];
                        float pB = zwa[q] + x0w[n1i] * w64a[q] + x1w[n1i] * w65a[q];
                        float sA = sigm(pA), sB = sigm(pB);
                        float dA = sA + pA * sA * (1.f - sA);
                        float dB = sB + pB * sB * (1.f - sB);
                        G1p[q] += r0 * dA + r1 * dB;
                    }
                }
            }
            __syncthreads();
        }

        // ---- reduce G1 partials across warps -> g1sums[i] ----
        #pragma unroll
        for (int q = 0; q < 4; q++) S.g1parts[g][jg4 + q][wg] = G1p[q];
        __syncthreads();
        {
            float4 p = *(const float4*)&S.g1parts[g][jj][0];
            S.g1sums[g][jj] = p.x + p.y + p.z + p.w;
        }
        __syncthreads();

        // ---- gz[k] = sum_i g1sums[i] * Wd1[k][i] (warp-coop, global weights) ----
        {
            int warpg = jj >> 5, lane = jj & 31;
            for (int kk = 0; kk < 16; kk++) {
                int k = warpg * 16 + kk;
                float a = 0.f;
                #pragma unroll
                for (int q = 0; q < 4; q++) {
                    int i = q * 32 + lane;
                    a += S.g1sums[g][i] * Wd1g[k * 128 + i];
                }
                #pragma unroll
                for (int off = 16; off > 0; off >>= 1)
                    a += __shfl_xor_sync(0xffffffffu, a, off);
                if (lane == 0) S.gzs[k * 4 + g] = a;
            }
        }
        __syncthreads();

        // ---- drift MLP (block-cooperative over 4 batch elements) ----
        if (tid < 128) {
            float4 acc = *(const float4*)&S.c1s[jj * 4];
            #pragma unroll 4
            for (int k = 0; k < 64; k++) {
                float w = Wf1g[k * 128 + jj];
                float4 zv = *(const float4*)&S.zs[k * 4];
                acc.x += w * zv.x; acc.y += w * zv.y; acc.z += w * zv.z; acc.w += w * zv.w;
            }
            float tw = t * wtj;
            acc.x = silu_f(acc.x + tw); acc.y = silu_f(acc.y + tw);
            acc.z = silu_f(acc.z + tw); acc.w = silu_f(acc.w + tw);
            *(float4*)&S.f1s[jj * 4] = acc;
        }
        __syncthreads();
        if (tid < 128) {
            float4 acc = make_float4(bf2j, bf2j, bf2j, bf2j);
            #pragma unroll 4
            for (int i = 0; i < 128; i++) {
                float w = Wf2g[i * 128 + jj];
                float4 v = *(const float4*)&S.f1s[i * 4];
                acc.x += w * v.x; acc.y += w * v.y; acc.z += w * v.z; acc.w += w * v.w;
            }
            acc.x = silu_f(acc.x); acc.y = silu_f(acc.y);
            acc.z = silu_f(acc.z); acc.w = silu_f(acc.w);
            *(float4*)&S.f2s[jj * 4] = acc;
        }
        __syncthreads();
        if (tid < 64) {
            int k = tid;
            float bf3k = bf3g[k];
            float4 acc = make_float4(bf3k, bf3k, bf3k, bf3k);
            #pragma unroll 4
            for (int i = 0; i < 128; i++) {
                float w = Wf3g[i * 64 + k];
                float4 v = *(const float4*)&S.f2s[i * 4];
                acc.x += w * v.x; acc.y += w * v.y; acc.z += w * v.z; acc.w += w * v.w;
            }
            float bvals[4] = {acc.x, acc.y, acc.z, acc.w};
            #pragma unroll
            for (int gg = 0; gg < 4; gg++) {
                float zold = S.zs[k * 4 + gg];
                float gv = zold + t * S.gzs[k * 4 + gg];
                gv = fminf(fmaxf(gv, -100.f), 100.f);
                float nz = noiseg[((size_t)s * BQ + (b0 + gg)) * 64 + k];
                S.zs[k * 4 + gg] = zold + (bvals[gg] - gv) * dtf + dcf * nz;
            }
        }
        __syncthreads();
    }

    // ---- write z_final ----
    for (int idx = jj; idx < 64; idx += 128)
        outg[(size_t)b * 64 + idx] = S.zs[idx * 4 + g];
}

// ===================== launcher =====================
extern "C" void kernel_launch(void* const* d_in, const int* in_sizes, int n_in,
                              void* d_out, int out_size)
{
    const float* x_ctx  = (const float*)d_in[0];
    const float* y_ctx  = (const float*)d_in[1];
    const float* mask   = (const float*)d_in[2];
    const float* z0     = (const float*)d_in[3];
    const float* noises = (const float*)d_in[4];
    const float* We1 = (const float*)d_in[5];  const float* be1 = (const float*)d_in[6];
    const float* We2 = (const float*)d_in[7];  const float* be2 = (const float*)d_in[8];
    const float* We3 = (const float*)d_in[9];  const float* be3 = (const float*)d_in[10];
    const float* Wd1 = (const float*)d_in[11]; const float* bd1 = (const float*)d_in[12];
    const float* Wd2 = (const float*)d_in[13]; const float* bd2 = (const float*)d_in[14];
    const float* Wd3 = (const float*)d_in[15]; const float* bd3 = (const float*)d_in[16];
    const float* Wf1 = (const float*)d_in[17]; const float* bf1 = (const float*)d_in[18];
    const float* Wf2 = (const float*)d_in[19]; const float* bf2 = (const float*)d_in[20];
    const float* Wf3 = (const float*)d_in[21]; const float* bf3 = (const float*)d_in[22];
    float* out = (float*)d_out;

    int steps = in_sizes[4] / (BQ * ZD);
    if (steps <= 0) steps = 20;
    float dtf = (float)(1.0 / (double)steps);
    float dcf = (float)sqrt(2.0 / (double)steps);

    cudaFuncSetAttribute(enc_kernel, cudaFuncAttributeMaxDynamicSharedMemorySize,
                         (int)sizeof(EncSmem));
    cudaFuncSetAttribute(main_kernel, cudaFuncAttributeMaxDynamicSharedMemorySize,
                         (int)sizeof(MainSmem));

    enc_kernel<<<BQ / 4, 512, sizeof(EncSmem)>>>(
        x_ctx, y_ctx, mask, We1, be1, We2, be2, We3, be3);

    main_kernel<<<BQ / 4, 512, sizeof(MainSmem)>>>(
        x_ctx, y_ctx, mask, z0, noises,
        Wd1, bd1, Wd2, bd2, Wd3, bd3,
        Wf1, bf1, Wf2, bf2, Wf3, bf3,
        out, steps, dtf, dcf);
}